// round 2
// baseline (speedup 1.0000x reference)
#include <cuda_runtime.h>
#include <cuda_bf16.h>
#include <cstdint>

// Problem constants (fixed by reference setup_inputs)
#define B_   16
#define D_   256
#define H_   32
#define W_   32
#define S_   1024            // H*W
#define NTOK 16384           // B*S
#define KC   8192            // codebook size
#define BDS  4194304         // B*D*S

// Tiling for the argmin (distance) kernel
#define TM   128             // tokens per block
#define TK   128             // codes per k-tile
#define DC   64              // d-chunk streamed through smem
#define NCHUNK ((KC / TK) * (D_ / DC))   // 256 total (k-tile, d-chunk) steps

#define XS_ELEMS (D_ * TM)       // 32768 floats = 128 KB
#define ES_ELEMS (DC * TK)       // 8192 floats  = 32 KB per buffer
#define SMEM_BYTES ((XS_ELEMS + 2 * ES_ELEMS) * sizeof(float))  // 192 KB

// Device scratch (no allocations allowed)
__device__ float g_csq[KC];
__device__ int   g_ind[NTOK];

// ---- packed fp32x2 helpers (FFMA2 path ptxas won't emit from C++) ----------
__device__ __forceinline__ unsigned long long packdup(float v) {
    unsigned long long r;
    asm("mov.b64 %0, {%1, %1};" : "=l"(r) : "f"(v));
    return r;
}
__device__ __forceinline__ void fma2(unsigned long long& d,
                                     unsigned long long a,
                                     unsigned long long b) {
    asm("fma.rn.f32x2 %0, %1, %2, %0;" : "+l"(d) : "l"(a), "l"(b));
}
__device__ __forceinline__ void unpack2(unsigned long long v, float& a, float& b) {
    asm("mov.b64 {%0, %1}, %2;" : "=f"(a), "=f"(b) : "l"(v));
}

// ---------------------------------------------------------------------------
// Kernel A: c[k] = ||e_k||^2  (E is [D, K] row-major, column k strided by K)
// ---------------------------------------------------------------------------
__global__ void vq_csq_kernel(const float* __restrict__ E) {
    int k = blockIdx.x * blockDim.x + threadIdx.x;
    if (k >= KC) return;
    float a = 0.f;
#pragma unroll 8
    for (int d = 0; d < D_; ++d) {
        float v = E[(size_t)d * KC + k];
        a = fmaf(v, v, a);
    }
    g_csq[k] = a;
}

// ---------------------------------------------------------------------------
// Kernel B: per-token argmin_k ( c_k - 2 * x·e_k )
//   256 threads = 16 (token groups) x 16 (code groups); 8x8 microtile/thread.
//   Token pairs packed -> fma.rn.f32x2 (2 MACs/issue on the fma pipe).
//   E streamed through double-buffered smem with register-staged prefetch.
// ---------------------------------------------------------------------------
__global__ __launch_bounds__(256, 1)
void vq_argmin_kernel(const float* __restrict__ x, const float* __restrict__ E) {
    extern __shared__ float smem[];
    float* xs = smem;                     // [D_][TM]
    float* es = smem + XS_ELEMS;          // [2][DC][TK]

    const int tid = threadIdx.x;
    const int ty  = tid >> 4;             // 0..15 token group
    const int tx  = tid & 15;             // 0..15 code group
    const int row0 = ty * 8;
    const int col0 = tx * 8;

    const int n0 = blockIdx.x * TM;       // first token of this block
    const int b  = n0 >> 10;              // /S_
    const int s0 = n0 & (S_ - 1);
    const size_t xbase = ((size_t)b * D_) * S_ + s0;

    // Load resident x tile: xs[d][t] = x[b, d, s0+t]
    for (int idx = tid; idx < XS_ELEMS; idx += 256) {
        int d = idx >> 7;                 // /TM
        int t = idx & (TM - 1);
        xs[idx] = x[xbase + (size_t)d * S_ + t];
    }

    // E-chunk streaming geometry: chunk c -> k0 = (c>>2)*TK, dc = (c&3)*DC.
    // Per thread: 32 elements, idx = r*256 + tid; dd = 2r + (tid>>7), j = tid&127.
    const int jj     = tid & 127;
    const int ddbase = tid >> 7;

    float stage[32];
    // Prefetch chunk 0 (k0=0, dc=0) into registers, then smem buffer 0.
    {
        const float* ep = E + (size_t)ddbase * KC + jj;
#pragma unroll
        for (int r = 0; r < 32; ++r) stage[r] = ep[(size_t)(2 * r) * KC];
    }
#pragma unroll
    for (int r = 0; r < 32; ++r) es[r * 256 + tid] = stage[r];
    __syncthreads();

    float best[8];
    int   bidx[8];
#pragma unroll
    for (int i = 0; i < 8; ++i) { best[i] = 3.402823466e+38f; bidx[i] = 0; }

    unsigned long long acc[4][8];         // token-pair i2 (tokens 2*i2, 2*i2+1) x code j
#pragma unroll
    for (int i2 = 0; i2 < 4; ++i2)
#pragma unroll
        for (int j = 0; j < 8; ++j) acc[i2][j] = 0ULL;

    for (int c = 0; c < NCHUNK; ++c) {
        const int buf = c & 1;
        const bool havenext = (c + 1) < NCHUNK;

        // Prefetch next chunk into registers (overlaps the compute below).
        if (havenext) {
            const int nc  = c + 1;
            const int k0n = (nc >> 2) * TK;
            const int dcn = (nc & 3) * DC;
            const float* ep = E + (size_t)(dcn + ddbase) * KC + k0n + jj;
#pragma unroll
            for (int r = 0; r < 32; ++r) stage[r] = ep[(size_t)(2 * r) * KC];
        }

        // Compute current chunk from es[buf].
        const int dcbase = (c & 3) * DC;
        const float* esb = es + (size_t)buf * ES_ELEMS;
#pragma unroll 8
        for (int dd = 0; dd < DC; ++dd) {
            const float* xrow = xs + (size_t)(dcbase + dd) * TM + row0;
            const float* erow = esb + (size_t)dd * TK + col0;
            // x token-pairs load packed directly (consecutive tokens contiguous).
            ulonglong2 xv0 = *(const ulonglong2*)(xrow);
            ulonglong2 xv1 = *(const ulonglong2*)(xrow + 4);
            unsigned long long xp[4] = {xv0.x, xv0.y, xv1.x, xv1.y};
            float4 u0 = *(const float4*)(erow);
            float4 u1 = *(const float4*)(erow + 4);
            unsigned long long ed[8];
            ed[0] = packdup(u0.x); ed[1] = packdup(u0.y);
            ed[2] = packdup(u0.z); ed[3] = packdup(u0.w);
            ed[4] = packdup(u1.x); ed[5] = packdup(u1.y);
            ed[6] = packdup(u1.z); ed[7] = packdup(u1.w);
#pragma unroll
            for (int i2 = 0; i2 < 4; ++i2)
#pragma unroll
                for (int j = 0; j < 8; ++j)
                    fma2(acc[i2][j], xp[i2], ed[j]);
        }

        // End of a k-tile: fold into running per-token argmin, reset acc.
        if ((c & 3) == 3) {
            const int k0 = (c >> 2) * TK;
            float cv[8];
#pragma unroll
            for (int j = 0; j < 8; ++j) cv[j] = g_csq[k0 + col0 + j];
#pragma unroll
            for (int i2 = 0; i2 < 4; ++i2) {
#pragma unroll
                for (int j = 0; j < 8; ++j) {
                    float a0, a1;
                    unpack2(acc[i2][j], a0, a1);
                    float m0 = fmaf(-2.f, a0, cv[j]);
                    float m1 = fmaf(-2.f, a1, cv[j]);
                    int i = 2 * i2;
                    if (m0 < best[i])     { best[i]     = m0; bidx[i]     = k0 + col0 + j; }
                    if (m1 < best[i + 1]) { best[i + 1] = m1; bidx[i + 1] = k0 + col0 + j; }
                    acc[i2][j] = 0ULL;
                }
            }
        }

        // Commit prefetched chunk to the other buffer; one sync per chunk.
        if (havenext) {
            float* esn = es + (size_t)(buf ^ 1) * ES_ELEMS;
#pragma unroll
            for (int r = 0; r < 32; ++r) esn[r * 256 + tid] = stage[r];
            __syncthreads();
        }
    }

    // Reduce across the 16 code-group lanes (contiguous 16-lane segments).
    // Prefer lower index on exact ties (matches jnp.argmin first-occurrence).
#pragma unroll
    for (int i = 0; i < 8; ++i) {
        float bv = best[i];
        int   bi = bidx[i];
        for (int off = 8; off >= 1; off >>= 1) {
            float ov = __shfl_xor_sync(0xffffffffu, bv, off, 16);
            int   oi = __shfl_xor_sync(0xffffffffu, bi, off, 16);
            if (ov < bv || (ov == bv && oi < bi)) { bv = ov; bi = oi; }
        }
        if (tx == 0) g_ind[n0 + row0 + i] = bi;
    }
}

// ---------------------------------------------------------------------------
// Kernel C: outputs.
//   out[0 : BDS)        = quantized_x_d = x + (q - x)   (exact fp32 op order)
//   out[BDS : 2*BDS)    = quantized_x   = q
//   out[2*BDS : +NTOK)  = ind (as float)
// ---------------------------------------------------------------------------
__global__ void vq_gather_kernel(const float* __restrict__ x,
                                 const float* __restrict__ E,
                                 float* __restrict__ out) {
    size_t tid = (size_t)blockIdx.x * blockDim.x + threadIdx.x;  // D_*NTOK total
    int n = (int)(tid & (NTOK - 1));
    int d = (int)(tid >> 14);            // /NTOK
    int idx = g_ind[n];
    int b = n >> 10;                     // /S_
    int s = n & (S_ - 1);
    float q  = E[(size_t)d * KC + idx];
    size_t xo = ((size_t)b * D_ + d) * S_ + s;
    float xv = x[xo];
    out[xo]        = xv + (q - xv);      // straight-through: replicate rounding
    out[BDS + xo]  = q;
    if (d == 0) out[2 * (size_t)BDS + n] = (float)idx;
}

// ---------------------------------------------------------------------------
extern "C" void kernel_launch(void* const* d_in, const int* in_sizes, int n_in,
                              void* d_out, int out_size) {
    const float* x = (const float*)d_in[0];   // [B, D, H, W] fp32
    const float* E = (const float*)d_in[1];   // [D, K] fp32
    float* out = (float*)d_out;

    cudaFuncSetAttribute(vq_argmin_kernel,
                         cudaFuncAttributeMaxDynamicSharedMemorySize,
                         (int)SMEM_BYTES);

    vq_csq_kernel<<<KC / 256, 256>>>(E);
    vq_argmin_kernel<<<NTOK / TM, 256, SMEM_BYTES>>>(x, E);
    vq_gather_kernel<<<(D_ * NTOK) / 256, 256>>>(x, E, out);
}

// round 5
// speedup vs baseline: 3.6860x; 3.6860x over previous
#include <cuda_runtime.h>
#include <cuda_fp16.h>
#include <cstdint>

// Problem constants
#define B_    16
#define D_    256
#define S_    1024
#define NTOK  16384
#define KC    8192
#define BDS   4194304

#define MB_TOT (NTOK / 16)        // 1024 token blocks of 16
#define KS_TOT (D_ / 16)          // 16 k-steps of 16
#define NB_TOT (KC / 8)           // 1024 code blocks of 8

// Main kernel tiling
#define MT     128                // tokens per block
#define NT     128                // codes per n-tile
#define NTILES (KC / NT)          // 64
#define TSTEPS (NTILES * KS_TOT)  // 1024 pipeline steps

// smem layout (bytes)
#define SMEM_A_BYTES 131072       // [2 h][8 mb][16 ks][32 lane][4] u32
#define SMEM_B_BYTES 16384        // [2 buf][2 h][16 nb][32 lane][2] u32
#define SMEM_RED     1024         // 128 x u64
#define SMEM_MAIN (SMEM_A_BYTES + SMEM_B_BYTES + SMEM_RED)

// Device scratch (allocations forbidden)
__device__ uint32_t g_Ah[MB_TOT * KS_TOT * 32 * 4];   // 8 MB
__device__ uint32_t g_Al[MB_TOT * KS_TOT * 32 * 4];   // 8 MB
__device__ uint32_t g_Bh[NB_TOT * KS_TOT * 32 * 2];   // 4 MB
__device__ uint32_t g_Bl[NB_TOT * KS_TOT * 32 * 2];   // 4 MB
__device__ float    g_csq[KC];
__device__ int      g_ind[NTOK];

// ---------------------------- helpers --------------------------------------
__device__ __forceinline__ uint32_t smem_u32(const void* p) {
    uint32_t a;
    asm("{ .reg .u64 t; cvta.to.shared.u64 t, %1; cvt.u32.u64 %0, t; }" : "=r"(a) : "l"(p));
    return a;
}
__device__ __forceinline__ void cpasync16(uint32_t dst, const void* src) {
    asm volatile("cp.async.cg.shared.global [%0], [%1], 16;" :: "r"(dst), "l"(src));
}
__device__ __forceinline__ void mma16816(float* c, const uint32_t* a, const uint32_t* b) {
    asm volatile("mma.sync.aligned.m16n8k16.row.col.f32.f16.f16.f32 "
                 "{%0,%1,%2,%3}, {%4,%5,%6,%7}, {%8,%9}, {%0,%1,%2,%3};"
                 : "+f"(c[0]), "+f"(c[1]), "+f"(c[2]), "+f"(c[3])
                 : "r"(a[0]), "r"(a[1]), "r"(a[2]), "r"(a[3]), "r"(b[0]), "r"(b[1]));
}
__device__ __forceinline__ uint32_t pack_h2(__half lo, __half hi) {
    __half2 h = __halves2half2(lo, hi);
    return *reinterpret_cast<uint32_t*>(&h);
}
__device__ __forceinline__ void split16(float v, __half& h, __half& l) {
    h = __float2half_rn(v);
    l = __float2half_rn(v - __half2float(h));
}
__device__ __forceinline__ unsigned int fkey(float f) {
    unsigned u = __float_as_uint(f);
    return (u & 0x80000000u) ? ~u : (u | 0x80000000u);
}

// ---------------------------------------------------------------------------
// Split x into fp16 hi/lo A-fragments (mma m16n8k16 row-major A layout).
// g_A?[mb][ks][lane][reg]: reg r, half h element = A[row][col] with
//   row = gid + (r&1)*8 ; col = ks*16 + tig*2 + h + (r>>1)*8 ; gid=lane>>2,tig=lane&3
// ---------------------------------------------------------------------------
__global__ void vq_split_x(const float* __restrict__ x) {
    __shared__ float xs[D_ * 16];            // [d][tok]
    const int mb = blockIdx.x;
    const int t0 = mb * 16;
    const int b  = t0 >> 10;
    const int s0 = t0 & (S_ - 1);
    const int tid = threadIdx.x;

    for (int i = tid; i < D_ * 16; i += 256) {
        int d = i >> 4, tok = i & 15;
        xs[d * 16 + tok] = x[((size_t)b * D_ + d) * S_ + s0 + tok];
    }
    __syncthreads();

    const size_t obase = (size_t)mb * (KS_TOT * 32 * 4);
    for (int oi = tid; oi < KS_TOT * 32 * 4; oi += 256) {
        int ks = oi >> 7, rem = oi & 127;
        int lane = rem >> 2, r = rem & 3;
        int gid = lane >> 2, tig = lane & 3;
        int row = gid + (r & 1) * 8;
        int c0  = ks * 16 + tig * 2 + (r >> 1) * 8;
        float v0 = xs[c0 * 16 + row];
        float v1 = xs[(c0 + 1) * 16 + row];
        __half h0, l0, h1, l1;
        split16(v0, h0, l0);
        split16(v1, h1, l1);
        g_Ah[obase + oi] = pack_h2(h0, h1);
        g_Al[obase + oi] = pack_h2(l0, l1);
    }
}

// ---------------------------------------------------------------------------
// Split E into fp16 hi/lo B-fragments (mma m16n8k16 col-major B layout).
// g_B?[nb][ks][lane][reg]: reg r, half h element = B[krow][col] with
//   krow = ks*16 + tig*2 + h + r*8 ; col(code) = nb*8 + gid
// ---------------------------------------------------------------------------
__global__ void vq_split_e(const float* __restrict__ E) {
    const int nb0 = blockIdx.x * 16;         // 16 nbs per block
    const int tid = threadIdx.x;
    for (int oi = tid; oi < 16 * KS_TOT * 32 * 2; oi += 256) {
        int nbL = oi >> 10, rem = oi & 1023;
        int ks = rem >> 6, rem2 = rem & 63;
        int lane = rem2 >> 1, r = rem2 & 1;
        int gid = lane >> 2, tig = lane & 3;
        int k   = (nb0 + nbL) * 8 + gid;     // code index
        int d0  = ks * 16 + tig * 2 + r * 8;
        float v0 = E[(size_t)d0 * KC + k];
        float v1 = E[(size_t)(d0 + 1) * KC + k];
        __half h0, l0, h1, l1;
        split16(v0, h0, l0);
        split16(v1, h1, l1);
        size_t o = (size_t)(nb0 + nbL) * (KS_TOT * 32 * 2) + (rem);
        g_Bh[o] = pack_h2(h0, h1);
        g_Bl[o] = pack_h2(l0, l1);
    }
}

// ---------------------------------------------------------------------------
__global__ void vq_csq_kernel(const float* __restrict__ E) {
    int k = blockIdx.x * blockDim.x + threadIdx.x;
    float a = 0.f;
#pragma unroll 8
    for (int d = 0; d < D_; ++d) {
        float v = E[(size_t)d * KC + k];
        a = fmaf(v, v, a);
    }
    g_csq[k] = a;
}

// ---------------------------------------------------------------------------
// Main kernel: distances via fp16-split mma.sync, fused running argmin.
// ---------------------------------------------------------------------------
__global__ __launch_bounds__(256, 1) void vq_mma_kernel() {
    extern __shared__ char smem[];
    uint32_t* As = (uint32_t*)smem;
    uint32_t* Bs = (uint32_t*)(smem + SMEM_A_BYTES);
    unsigned long long* red = (unsigned long long*)(smem + SMEM_A_BYTES + SMEM_B_BYTES);
    const uint32_t sA = smem_u32(As);
    const uint32_t sB = smem_u32(Bs);

    const int tid = threadIdx.x;
    const int wid = tid >> 5, lane = tid & 31;
    const int gid = lane >> 2, tig = lane & 3;
    const int mwarp = wid >> 2, nwarp = wid & 3;
    const int mb0 = blockIdx.x * 8;
    const int n0  = blockIdx.x * MT;

    for (int i = tid; i < MT; i += 256) red[i] = 0xFFFFFFFFFFFFFFFFULL;

    // Resident A tile (hi+lo, 128 KB) via cp.async.
    {
        const uint32_t* srcH = g_Ah + (size_t)mb0 * (KS_TOT * 32 * 4);
        const uint32_t* srcL = g_Al + (size_t)mb0 * (KS_TOT * 32 * 4);
        for (int u = tid; u < 4096; u += 256) {
            cpasync16(sA + u * 16, srcH + u * 4);
            cpasync16(sA + 65536 + u * 16, srcL + u * 4);
        }
    }
    // Stage 0 of B.
    {
        int i = tid >> 4, off = tid & 15;
        size_t go = ((size_t)(i) * KS_TOT) * 64 + off * 4;
        cpasync16(sB + i * 256 + off * 16, g_Bh + go);
        cpasync16(sB + 4096 + i * 256 + off * 16, g_Bl + go);
    }
    asm volatile("cp.async.commit_group;" ::: "memory");

    float best[4][2];
    int   bidx[4][2];
#pragma unroll
    for (int mf = 0; mf < 4; ++mf)
#pragma unroll
        for (int hh = 0; hh < 2; ++hh) { best[mf][hh] = 3.402823466e+38f; bidx[mf][hh] = 0; }

    float acc[4][4][4];

    for (int s = 0; s < TSTEPS; ++s) {
        const int ntile = s >> 4, ks = s & 15;
        const int buf = s & 1;

        // Drain stage s (and A on s==0), make visible to all warps.
        asm volatile("cp.async.wait_group 0;" ::: "memory");
        __syncthreads();

        // Issue stage s+1 (safe: all warps finished reading this buffer at s-1).
        if (s + 1 < TSTEPS) {
            const int ns = s + 1;
            const int nb0n = (ns >> 4) * 16;
            const int ksn  = ns & 15;
            int i = tid >> 4, off = tid & 15;
            size_t go = ((size_t)(nb0n + i) * KS_TOT + ksn) * 64 + off * 4;
            uint32_t d0 = sB + ((buf ^ 1) * 8192) + i * 256 + off * 16;
            cpasync16(d0, g_Bh + go);
            cpasync16(d0 + 4096, g_Bl + go);
        }
        asm volatile("cp.async.commit_group;" ::: "memory");

        if (ks == 0) {
#pragma unroll
            for (int mf = 0; mf < 4; ++mf)
#pragma unroll
                for (int nf = 0; nf < 4; ++nf)
#pragma unroll
                    for (int c = 0; c < 4; ++c) acc[mf][nf][c] = 0.f;
        }

        // Operand fragments from smem.
        // A: [h][mb][ks][lane][4] u32; hi at u32 0, lo at u32 16384.
        // B buffer: 2048 u32 per buffer; [h][nb][lane][2] u32, lo at +1024.
        uint32_t ah[4][4], al[4][4], bh[4][2], bl[4][2];
#pragma unroll
        for (int mf = 0; mf < 4; ++mf) {
            int idx = (((mwarp * 4 + mf) * 16 + ks) * 32 + lane) * 4;
            *(uint4*)ah[mf] = *(const uint4*)(As + idx);
            *(uint4*)al[mf] = *(const uint4*)(As + 16384 + idx);
        }
#pragma unroll
        for (int nf = 0; nf < 4; ++nf) {
            int idx = buf * 2048 + ((nwarp * 4 + nf) * 32 + lane) * 2;
            *(uint2*)bh[nf] = *(const uint2*)(Bs + idx);
            *(uint2*)bl[nf] = *(const uint2*)(Bs + 1024 + idx);
        }

        // 48 HMMAs: hi*hi + hi*lo + lo*hi.
#pragma unroll
        for (int mf = 0; mf < 4; ++mf)
#pragma unroll
            for (int nf = 0; nf < 4; ++nf) {
                mma16816(acc[mf][nf], ah[mf], bh[nf]);
                mma16816(acc[mf][nf], ah[mf], bl[nf]);
                mma16816(acc[mf][nf], al[mf], bh[nf]);
            }

        // End of n-tile: fold distances into running argmin (k ascending).
        if (ks == 15) {
#pragma unroll
            for (int mf = 0; mf < 4; ++mf) {
#pragma unroll
                for (int nf = 0; nf < 4; ++nf) {
                    const int k0 = ntile * NT + (nwarp * 4 + nf) * 8 + tig * 2;
                    float c0 = __ldg(&g_csq[k0]);
                    float c1 = __ldg(&g_csq[k0 + 1]);
                    float m00 = fmaf(-2.f, acc[mf][nf][0], c0);
                    float m01 = fmaf(-2.f, acc[mf][nf][1], c1);
                    float m10 = fmaf(-2.f, acc[mf][nf][2], c0);
                    float m11 = fmaf(-2.f, acc[mf][nf][3], c1);
                    if (m00 < best[mf][0]) { best[mf][0] = m00; bidx[mf][0] = k0; }
                    if (m01 < best[mf][0]) { best[mf][0] = m01; bidx[mf][0] = k0 + 1; }
                    if (m10 < best[mf][1]) { best[mf][1] = m10; bidx[mf][1] = k0; }
                    if (m11 < best[mf][1]) { best[mf][1] = m11; bidx[mf][1] = k0 + 1; }
                }
            }
        }
    }

    // Reduce across the 4 tig lanes (same rows), lower index wins ties.
#pragma unroll
    for (int mf = 0; mf < 4; ++mf) {
#pragma unroll
        for (int hh = 0; hh < 2; ++hh) {
            float bv = best[mf][hh];
            int   bi = bidx[mf][hh];
#pragma unroll
            for (int off = 1; off <= 2; off <<= 1) {
                float ov = __shfl_xor_sync(0xffffffffu, bv, off);
                int   oi = __shfl_xor_sync(0xffffffffu, bi, off);
                if (ov < bv || (ov == bv && oi < bi)) { bv = ov; bi = oi; }
            }
            if (tig == 0) {
                int row = mwarp * 64 + mf * 16 + gid + hh * 8;
                unsigned long long key =
                    ((unsigned long long)fkey(bv) << 32) | (unsigned)bi;
                atomicMin(&red[row], key);
            }
        }
    }
    __syncthreads();
    if (tid < MT) g_ind[n0 + tid] = (int)(red[tid] & 0xFFFFFFFFu);
}

// ---------------------------------------------------------------------------
// Outputs: quantized_x_d, quantized_x, ind (exact fp32 op order for STE).
// ---------------------------------------------------------------------------
__global__ void vq_gather_kernel(const float* __restrict__ x,
                                 const float* __restrict__ E,
                                 float* __restrict__ out) {
    size_t tid = (size_t)blockIdx.x * blockDim.x + threadIdx.x;
    int n = (int)(tid & (NTOK - 1));
    int d = (int)(tid >> 14);
    int idx = g_ind[n];
    int b = n >> 10;
    int s = n & (S_ - 1);
    float q = E[(size_t)d * KC + idx];
    size_t xo = ((size_t)b * D_ + d) * S_ + s;
    float xv = x[xo];
    out[xo]       = xv + (q - xv);
    out[BDS + xo] = q;
    if (d == 0) out[2 * (size_t)BDS + n] = (float)idx;
}

// ---------------------------------------------------------------------------
extern "C" void kernel_launch(void* const* d_in, const int* in_sizes, int n_in,
                              void* d_out, int out_size) {
    const float* x = (const float*)d_in[0];   // [B, D, H, W] fp32
    const float* E = (const float*)d_in[1];   // [D, K] fp32
    float* out = (float*)d_out;

    cudaFuncSetAttribute(vq_mma_kernel,
                         cudaFuncAttributeMaxDynamicSharedMemorySize, SMEM_MAIN);

    vq_split_x<<<MB_TOT, 256>>>(x);
    vq_split_e<<<NB_TOT / 16, 256>>>(E);
    vq_csq_kernel<<<KC / 256, 256>>>(E);
    vq_mma_kernel<<<NTOK / MT, 256, SMEM_MAIN>>>();
    vq_gather_kernel<<<(D_ * NTOK) / 256, 256>>>(x, E, out);
}

// round 6
// speedup vs baseline: 4.1809x; 1.1342x over previous
#include <cuda_runtime.h>
#include <cuda_fp16.h>
#include <cstdint>

// Problem constants
#define B_    16
#define D_    256
#define S_    1024
#define NTOK  16384
#define KC    8192
#define BDS   4194304

#define MB_TOT (NTOK / 16)        // 1024 token blocks of 16
#define KS_TOT (D_ / 16)          // 16 k-steps of 16
#define NB_TOT (KC / 8)           // 1024 code blocks of 8

// Main kernel tiling
#define MT     128                // tokens per block
#define NT     128                // codes per n-tile
#define NTILES (KC / NT)          // 64
#define NITER  (NTILES * 8)       // 512 iterations, 2 k-steps each

// smem layout (bytes)
#define SMEM_A_BYTES 131072       // [2 h][8 mb][16 ks][32 lane][4] u32
#define B_STAGE_BYTES 16384       // [2 ksl][16 nb][32 lane][4] u32
#define SMEM_B_BYTES (3 * B_STAGE_BYTES)
#define SMEM_RED     1024         // 128 x u64
#define SMEM_MAIN (SMEM_A_BYTES + SMEM_B_BYTES + SMEM_RED)   // 181248

// Device scratch (allocations forbidden)
__device__ uint32_t g_Ah[MB_TOT * KS_TOT * 32 * 4];   // 8 MB
__device__ uint32_t g_Al[MB_TOT * KS_TOT * 32 * 4];   // 8 MB
__device__ uint32_t g_B [NB_TOT * KS_TOT * 32 * 4];   // 8 MB: {bh0,bh1,bl0,bl1}
__device__ float    g_csq[KC];
__device__ int      g_ind[NTOK];

// ---------------------------- helpers --------------------------------------
__device__ __forceinline__ uint32_t smem_u32(const void* p) {
    uint32_t a;
    asm("{ .reg .u64 t; cvta.to.shared.u64 t, %1; cvt.u32.u64 %0, t; }" : "=r"(a) : "l"(p));
    return a;
}
__device__ __forceinline__ void cpasync16(uint32_t dst, const void* src) {
    asm volatile("cp.async.cg.shared.global [%0], [%1], 16;" :: "r"(dst), "l"(src));
}
__device__ __forceinline__ void mma16816(float* c, const uint32_t* a, const uint32_t* b) {
    asm volatile("mma.sync.aligned.m16n8k16.row.col.f32.f16.f16.f32 "
                 "{%0,%1,%2,%3}, {%4,%5,%6,%7}, {%8,%9}, {%0,%1,%2,%3};"
                 : "+f"(c[0]), "+f"(c[1]), "+f"(c[2]), "+f"(c[3])
                 : "r"(a[0]), "r"(a[1]), "r"(a[2]), "r"(a[3]), "r"(b[0]), "r"(b[1]));
}
__device__ __forceinline__ uint32_t pack_h2(__half lo, __half hi) {
    __half2 h = __halves2half2(lo, hi);
    return *reinterpret_cast<uint32_t*>(&h);
}
__device__ __forceinline__ void split16(float v, __half& h, __half& l) {
    h = __float2half_rn(v);
    l = __float2half_rn(v - __half2float(h));
}
__device__ __forceinline__ unsigned int fkey(float f) {
    unsigned u = __float_as_uint(f);
    return (u & 0x80000000u) ? ~u : (u | 0x80000000u);
}

// ---------------------------------------------------------------------------
// Split x into fp16 hi/lo A-fragments (mma m16n8k16 row-major A layout).
// g_A?[mb][ks][lane][reg]: reg r, half h element = A[row][col] with
//   row = gid + (r&1)*8 ; col = ks*16 + tig*2 + h + (r>>1)*8
// ---------------------------------------------------------------------------
__global__ void vq_split_x(const float* __restrict__ x) {
    __shared__ float xs[D_ * 16];            // [d][tok]
    const int mb = blockIdx.x;
    const int t0 = mb * 16;
    const int b  = t0 >> 10;
    const int s0 = t0 & (S_ - 1);
    const int tid = threadIdx.x;

    for (int i = tid; i < D_ * 16; i += 256) {
        int d = i >> 4, tok = i & 15;
        xs[d * 16 + tok] = x[((size_t)b * D_ + d) * S_ + s0 + tok];
    }
    __syncthreads();

    const size_t obase = (size_t)mb * (KS_TOT * 32 * 4);
    for (int oi = tid; oi < KS_TOT * 32 * 4; oi += 256) {
        int ks = oi >> 7, rem = oi & 127;
        int lane = rem >> 2, r = rem & 3;
        int gid = lane >> 2, tig = lane & 3;
        int row = gid + (r & 1) * 8;
        int c0  = ks * 16 + tig * 2 + (r >> 1) * 8;
        float v0 = xs[c0 * 16 + row];
        float v1 = xs[(c0 + 1) * 16 + row];
        __half h0, l0, h1, l1;
        split16(v0, h0, l0);
        split16(v1, h1, l1);
        g_Ah[obase + oi] = pack_h2(h0, h1);
        g_Al[obase + oi] = pack_h2(l0, l1);
    }
}

// ---------------------------------------------------------------------------
// Split E into interleaved fp16 hi/lo B-fragments (m16n8k16 col-major B).
// g_B[((nb*16+ks)*32+lane)*4 + {0,1}] = bh regs, + {2,3} = bl regs.
// Element (r, h): krow = ks*16 + tig*2 + h + r*8 ; code = nb*8 + gid
// ---------------------------------------------------------------------------
__global__ void vq_split_e(const float* __restrict__ E) {
    int gidx = blockIdx.x * 256 + threadIdx.x;    // 0 .. NB_TOT*16*32
    int lane = gidx & 31;
    int ks   = (gidx >> 5) & 15;
    int nb   = gidx >> 9;
    int gid = lane >> 2, tig = lane & 3;
    int k = nb * 8 + gid;
    uint32_t frag[4];
#pragma unroll
    for (int r = 0; r < 2; ++r) {
        int d0 = ks * 16 + tig * 2 + r * 8;
        float v0 = E[(size_t)d0 * KC + k];
        float v1 = E[(size_t)(d0 + 1) * KC + k];
        __half h0, l0, h1, l1;
        split16(v0, h0, l0);
        split16(v1, h1, l1);
        frag[r]     = pack_h2(h0, h1);
        frag[2 + r] = pack_h2(l0, l1);
    }
    *(uint4*)&g_B[(size_t)gidx * 4] = *(uint4*)frag;
}

// ---------------------------------------------------------------------------
__global__ void vq_csq_kernel(const float* __restrict__ E) {
    int k = blockIdx.x * blockDim.x + threadIdx.x;
    float a = 0.f;
#pragma unroll 8
    for (int d = 0; d < D_; ++d) {
        float v = E[(size_t)d * KC + k];
        a = fmaf(v, v, a);
    }
    g_csq[k] = a;
}

// ---------------------------------------------------------------------------
// Main kernel: fp16-split mma.sync, 3-stage cp.async pipeline, fused argmin.
// ---------------------------------------------------------------------------
__device__ __forceinline__ void issue_stageB(uint32_t dst, int tgt, int tid) {
    const int ntile = tgt >> 3, ks0 = (tgt & 7) * 2;
#pragma unroll
    for (int u = 0; u < 4; ++u) {
        int flat = u * 256 + tid;            // 0..1023 units of 16B
        int slab = flat >> 5;                // ksl*16 + nbl
        int ksl  = slab >> 4, nbl = slab & 15;
        int off  = flat & 31;
        const uint32_t* src = g_B +
            ((size_t)((ntile * 16 + nbl) * 16 + ks0 + ksl)) * 128 + off * 4;
        cpasync16(dst + flat * 16, src);
    }
}

__global__ __launch_bounds__(256, 1) void vq_mma_kernel() {
    extern __shared__ char smem[];
    uint32_t* As = (uint32_t*)smem;
    uint32_t* Bs = (uint32_t*)(smem + SMEM_A_BYTES);
    unsigned long long* red = (unsigned long long*)(smem + SMEM_A_BYTES + SMEM_B_BYTES);
    const uint32_t sA = smem_u32(As);
    const uint32_t sB = smem_u32(Bs);

    const int tid = threadIdx.x;
    const int wid = tid >> 5, lane = tid & 31;
    const int gid = lane >> 2, tig = lane & 3;
    const int mwarp = wid >> 2, nwarp = wid & 3;
    const int mb0 = blockIdx.x * 8;
    const int n0  = blockIdx.x * MT;

    for (int i = tid; i < MT; i += 256) red[i] = 0xFFFFFFFFFFFFFFFFULL;

    // Prologue: A resident tile + B stage 0 (one group), then B stage 1.
    {
        const uint32_t* srcH = g_Ah + (size_t)mb0 * (KS_TOT * 32 * 4);
        const uint32_t* srcL = g_Al + (size_t)mb0 * (KS_TOT * 32 * 4);
        for (int u = tid; u < 4096; u += 256) {
            cpasync16(sA + u * 16, srcH + u * 4);
            cpasync16(sA + 65536 + u * 16, srcL + u * 4);
        }
        issue_stageB(sB, 0, tid);
        asm volatile("cp.async.commit_group;" ::: "memory");
        issue_stageB(sB + B_STAGE_BYTES, 1, tid);
        asm volatile("cp.async.commit_group;" ::: "memory");
    }

    float best[4][2];
    int   bidx[4][2];
#pragma unroll
    for (int mf = 0; mf < 4; ++mf)
#pragma unroll
        for (int hh = 0; hh < 2; ++hh) { best[mf][hh] = 3.402823466e+38f; bidx[mf][hh] = 0; }

    float acc[4][4][4];
    int buf = 0;

    for (int it = 0; it < NITER; ++it) {
        const int ntile = it >> 3, kspair = it & 7;

        // Stage `it` arrived (<=1 group may remain in flight).
        asm volatile("cp.async.wait_group 1;" ::: "memory");
        __syncthreads();

        // Prefetch stage it+2 into the buffer freed at iter it-1.
        if (it + 2 < NITER) {
            int nbuf = buf + 2; if (nbuf >= 3) nbuf -= 3;
            issue_stageB(sB + nbuf * B_STAGE_BYTES, it + 2, tid);
        }
        asm volatile("cp.async.commit_group;" ::: "memory");

        if (kspair == 0) {
#pragma unroll
            for (int mf = 0; mf < 4; ++mf)
#pragma unroll
                for (int nf = 0; nf < 4; ++nf)
#pragma unroll
                    for (int c = 0; c < 4; ++c) acc[mf][nf][c] = 0.f;
        }

        const uint32_t* Bbuf = Bs + buf * 4096;
#pragma unroll
        for (int ksl = 0; ksl < 2; ++ksl) {
            const int ks = kspair * 2 + ksl;
            uint32_t ah[4][4], al[4][4], bf[4][4];
#pragma unroll
            for (int mf = 0; mf < 4; ++mf) {
                int idx = (((mwarp * 4 + mf) * 16 + ks) * 32 + lane) * 4;
                *(uint4*)ah[mf] = *(const uint4*)(As + idx);
                *(uint4*)al[mf] = *(const uint4*)(As + 16384 + idx);
            }
#pragma unroll
            for (int nf = 0; nf < 4; ++nf) {
                int idx = ((ksl * 16 + nwarp * 4 + nf) * 32 + lane) * 4;
                *(uint4*)bf[nf] = *(const uint4*)(Bbuf + idx);
            }
#pragma unroll
            for (int mf = 0; mf < 4; ++mf)
#pragma unroll
                for (int nf = 0; nf < 4; ++nf) {
                    mma16816(acc[mf][nf], ah[mf], &bf[nf][0]);   // hi*hi
                    mma16816(acc[mf][nf], ah[mf], &bf[nf][2]);   // hi*lo
                    mma16816(acc[mf][nf], al[mf], &bf[nf][0]);   // lo*hi
                }
        }

        // End of n-tile: fold distances into running argmin (k ascending).
        if (kspair == 7) {
#pragma unroll
            for (int mf = 0; mf < 4; ++mf) {
#pragma unroll
                for (int nf = 0; nf < 4; ++nf) {
                    const int k0 = ntile * NT + (nwarp * 4 + nf) * 8 + tig * 2;
                    float c0 = __ldg(&g_csq[k0]);
                    float c1 = __ldg(&g_csq[k0 + 1]);
                    float m00 = fmaf(-2.f, acc[mf][nf][0], c0);
                    float m01 = fmaf(-2.f, acc[mf][nf][1], c1);
                    float m10 = fmaf(-2.f, acc[mf][nf][2], c0);
                    float m11 = fmaf(-2.f, acc[mf][nf][3], c1);
                    if (m00 < best[mf][0]) { best[mf][0] = m00; bidx[mf][0] = k0; }
                    if (m01 < best[mf][0]) { best[mf][0] = m01; bidx[mf][0] = k0 + 1; }
                    if (m10 < best[mf][1]) { best[mf][1] = m10; bidx[mf][1] = k0; }
                    if (m11 < best[mf][1]) { best[mf][1] = m11; bidx[mf][1] = k0 + 1; }
                }
            }
        }

        if (++buf == 3) buf = 0;
    }

    // Reduce across the 4 tig lanes (same rows), lower index wins ties.
#pragma unroll
    for (int mf = 0; mf < 4; ++mf) {
#pragma unroll
        for (int hh = 0; hh < 2; ++hh) {
            float bv = best[mf][hh];
            int   bi = bidx[mf][hh];
#pragma unroll
            for (int off = 1; off <= 2; off <<= 1) {
                float ov = __shfl_xor_sync(0xffffffffu, bv, off);
                int   oi = __shfl_xor_sync(0xffffffffu, bi, off);
                if (ov < bv || (ov == bv && oi < bi)) { bv = ov; bi = oi; }
            }
            if (tig == 0) {
                int row = mwarp * 64 + mf * 16 + gid + hh * 8;
                unsigned long long key =
                    ((unsigned long long)fkey(bv) << 32) | (unsigned)bi;
                atomicMin(&red[row], key);
            }
        }
    }
    __syncthreads();
    if (tid < MT) g_ind[n0 + tid] = (int)(red[tid] & 0xFFFFFFFFu);
}

// ---------------------------------------------------------------------------
// Outputs: quantized_x_d, quantized_x, ind (exact fp32 op order for STE).
// ---------------------------------------------------------------------------
__global__ void vq_gather_kernel(const float* __restrict__ x,
                                 const float* __restrict__ E,
                                 float* __restrict__ out) {
    size_t tid = (size_t)blockIdx.x * blockDim.x + threadIdx.x;
    int n = (int)(tid & (NTOK - 1));
    int d = (int)(tid >> 14);
    int idx = g_ind[n];
    int b = n >> 10;
    int s = n & (S_ - 1);
    float q = E[(size_t)d * KC + idx];
    size_t xo = ((size_t)b * D_ + d) * S_ + s;
    float xv = x[xo];
    out[xo]       = xv + (q - xv);
    out[BDS + xo] = q;
    if (d == 0) out[2 * (size_t)BDS + n] = (float)idx;
}

// ---------------------------------------------------------------------------
extern "C" void kernel_launch(void* const* d_in, const int* in_sizes, int n_in,
                              void* d_out, int out_size) {
    const float* x = (const float*)d_in[0];   // [B, D, H, W] fp32
    const float* E = (const float*)d_in[1];   // [D, K] fp32
    float* out = (float*)d_out;

    cudaFuncSetAttribute(vq_mma_kernel,
                         cudaFuncAttributeMaxDynamicSharedMemorySize, SMEM_MAIN);

    vq_split_x<<<MB_TOT, 256>>>(x);
    vq_split_e<<<(NB_TOT * 16 * 32) / 256, 256>>>(E);
    vq_csq_kernel<<<KC / 256, 256>>>(E);
    vq_mma_kernel<<<NTOK / MT, 256, SMEM_MAIN>>>();
    vq_gather_kernel<<<(D_ * NTOK) / 256, 256>>>(x, E, out);
}

// round 7
// speedup vs baseline: 4.9110x; 1.1746x over previous
#include <cuda_runtime.h>
#include <cuda_fp16.h>
#include <cstdint>

// Problem constants
#define B_    16
#define D_    256
#define S_    1024
#define NTOK  16384
#define KC    8192
#define BDS   4194304

#define MB_TOT (NTOK / 16)        // 1024 token blocks of 16
#define KS_TOT (D_ / 16)          // 16 k-steps of 16
#define NB_TOT (KC / 8)           // 1024 code blocks of 8

// Main kernel tiling
#define MT     128                // tokens per block
#define NT     128                // codes per n-tile
#define NTILES (KC / NT)          // 64
#define NITER  (NTILES * 8)       // 512 iterations, 2 k-steps each

// smem layout (bytes): A-tile (hi|lo) + reduction slots
#define SMEM_A_BYTES 131072       // [2 h][8 mb][16 ks][32 lane][4] u32
#define SMEM_RED     1024         // 128 x u64
#define SMEM_MAIN (SMEM_A_BYTES + SMEM_RED)

// Device scratch (allocations forbidden)
__device__ uint32_t g_Ah[MB_TOT * KS_TOT * 32 * 4];   // 8 MB
__device__ uint32_t g_Al[MB_TOT * KS_TOT * 32 * 4];   // 8 MB
__device__ uint32_t g_B [NB_TOT * KS_TOT * 32 * 4];   // 8 MB: {bh0,bh1,bl0,bl1}
__device__ float    g_csq[KC];
__device__ int      g_ind[NTOK];

// ---------------------------- helpers --------------------------------------
__device__ __forceinline__ uint32_t smem_u32(const void* p) {
    uint32_t a;
    asm("{ .reg .u64 t; cvta.to.shared.u64 t, %1; cvt.u32.u64 %0, t; }" : "=r"(a) : "l"(p));
    return a;
}
__device__ __forceinline__ void cpasync16(uint32_t dst, const void* src) {
    asm volatile("cp.async.cg.shared.global [%0], [%1], 16;" :: "r"(dst), "l"(src));
}
__device__ __forceinline__ void mma16816(float* c, const uint32_t* a, const uint32_t* b) {
    asm volatile("mma.sync.aligned.m16n8k16.row.col.f32.f16.f16.f32 "
                 "{%0,%1,%2,%3}, {%4,%5,%6,%7}, {%8,%9}, {%0,%1,%2,%3};"
                 : "+f"(c[0]), "+f"(c[1]), "+f"(c[2]), "+f"(c[3])
                 : "r"(a[0]), "r"(a[1]), "r"(a[2]), "r"(a[3]), "r"(b[0]), "r"(b[1]));
}
__device__ __forceinline__ uint32_t pack_h2(__half lo, __half hi) {
    __half2 h = __halves2half2(lo, hi);
    return *reinterpret_cast<uint32_t*>(&h);
}
__device__ __forceinline__ void split16(float v, __half& h, __half& l) {
    h = __float2half_rn(v);
    l = __float2half_rn(v - __half2float(h));
}
__device__ __forceinline__ unsigned int fkey(float f) {
    unsigned u = __float_as_uint(f);
    return (u & 0x80000000u) ? ~u : (u | 0x80000000u);
}

// ---------------------------------------------------------------------------
// Split x into fp16 hi/lo A-fragments (mma m16n8k16 row-major A layout).
// ---------------------------------------------------------------------------
__global__ void vq_split_x(const float* __restrict__ x) {
    __shared__ float xs[D_ * 16];            // [d][tok]
    const int mb = blockIdx.x;
    const int t0 = mb * 16;
    const int b  = t0 >> 10;
    const int s0 = t0 & (S_ - 1);
    const int tid = threadIdx.x;

    for (int i = tid; i < D_ * 16; i += 256) {
        int d = i >> 4, tok = i & 15;
        xs[d * 16 + tok] = x[((size_t)b * D_ + d) * S_ + s0 + tok];
    }
    __syncthreads();

    const size_t obase = (size_t)mb * (KS_TOT * 32 * 4);
    for (int oi = tid; oi < KS_TOT * 32 * 4; oi += 256) {
        int ks = oi >> 7, rem = oi & 127;
        int lane = rem >> 2, r = rem & 3;
        int gid = lane >> 2, tig = lane & 3;
        int row = gid + (r & 1) * 8;
        int c0  = ks * 16 + tig * 2 + (r >> 1) * 8;
        float v0 = xs[c0 * 16 + row];
        float v1 = xs[(c0 + 1) * 16 + row];
        __half h0, l0, h1, l1;
        split16(v0, h0, l0);
        split16(v1, h1, l1);
        g_Ah[obase + oi] = pack_h2(h0, h1);
        g_Al[obase + oi] = pack_h2(l0, l1);
    }
}

// ---------------------------------------------------------------------------
// Split E into interleaved fp16 hi/lo B-fragments (m16n8k16 col-major B).
// g_B[((nb*16+ks)*32+lane)*4 + {0,1}] = bh regs, + {2,3} = bl regs.
// ---------------------------------------------------------------------------
__global__ void vq_split_e(const float* __restrict__ E) {
    int gidx = blockIdx.x * 256 + threadIdx.x;    // 0 .. NB_TOT*16*32
    int lane = gidx & 31;
    int ks   = (gidx >> 5) & 15;
    int nb   = gidx >> 9;
    int gid = lane >> 2, tig = lane & 3;
    int k = nb * 8 + gid;
    uint32_t frag[4];
#pragma unroll
    for (int r = 0; r < 2; ++r) {
        int d0 = ks * 16 + tig * 2 + r * 8;
        float v0 = E[(size_t)d0 * KC + k];
        float v1 = E[(size_t)(d0 + 1) * KC + k];
        __half h0, l0, h1, l1;
        split16(v0, h0, l0);
        split16(v1, h1, l1);
        frag[r]     = pack_h2(h0, h1);
        frag[2 + r] = pack_h2(l0, l1);
    }
    *(uint4*)&g_B[(size_t)gidx * 4] = *(uint4*)frag;
}

// ---------------------------------------------------------------------------
__global__ void vq_csq_kernel(const float* __restrict__ E) {
    int k = blockIdx.x * blockDim.x + threadIdx.x;
    float a = 0.f;
#pragma unroll 8
    for (int d = 0; d < D_; ++d) {
        float v = E[(size_t)d * KC + k];
        a = fmaf(v, v, a);
    }
    g_csq[k] = a;
}

// ---------------------------------------------------------------------------
// Main kernel: fp16-split mma.sync; A resident in smem, B register-pipelined
// via LDG.128 from L2 (fragment-major). NO barriers in the mainloop.
// ---------------------------------------------------------------------------
__device__ __forceinline__ void loadB(uint4* b, int it, int nwarp, int lane) {
    const int ntile = it >> 3, kspair = it & 7;
    const uint32_t* base = g_B +
        ((size_t)(((ntile * 16 + nwarp * 4) * 16 + kspair * 2) * 32 + lane)) * 4;
    // nf stride: 16*32*4 = 2048 u32 ; ksl stride: 32*4 = 128 u32
#pragma unroll
    for (int nf = 0; nf < 4; ++nf)
#pragma unroll
        for (int ksl = 0; ksl < 2; ++ksl)
            b[nf * 2 + ksl] = __ldg((const uint4*)(base + nf * 2048 + ksl * 128));
}

__global__ __launch_bounds__(256, 1) void vq_mma_kernel() {
    extern __shared__ char smem[];
    uint32_t* As = (uint32_t*)smem;
    unsigned long long* red = (unsigned long long*)(smem + SMEM_A_BYTES);
    const uint32_t sA = smem_u32(As);

    const int tid = threadIdx.x;
    const int wid = tid >> 5, lane = tid & 31;
    const int gid = lane >> 2, tig = lane & 3;
    const int mwarp = wid >> 2, nwarp = wid & 3;
    const int mb0 = blockIdx.x * 8;
    const int n0  = blockIdx.x * MT;

    for (int i = tid; i < MT; i += 256) red[i] = 0xFFFFFFFFFFFFFFFFULL;

    // Prologue: A resident tile (hi+lo, 128 KB) via cp.async; single barrier.
    {
        const uint32_t* srcH = g_Ah + (size_t)mb0 * (KS_TOT * 32 * 4);
        const uint32_t* srcL = g_Al + (size_t)mb0 * (KS_TOT * 32 * 4);
        for (int u = tid; u < 4096; u += 256) {
            cpasync16(sA + u * 16, srcH + u * 4);
            cpasync16(sA + 65536 + u * 16, srcL + u * 4);
        }
        asm volatile("cp.async.commit_group;" ::: "memory");
    }

    uint4 bnxt[8];
    loadB(bnxt, 0, nwarp, lane);              // overlaps the A cp.async

    asm volatile("cp.async.wait_group 0;" ::: "memory");
    __syncthreads();                           // last barrier before epilogue

    float best[4][2];
    int   bidx[4][2];
#pragma unroll
    for (int mf = 0; mf < 4; ++mf)
#pragma unroll
        for (int hh = 0; hh < 2; ++hh) { best[mf][hh] = 3.402823466e+38f; bidx[mf][hh] = 0; }

    float acc[4][4][4];

    for (int it = 0; it < NITER; ++it) {
        const int ntile = it >> 3, kspair = it & 7;

        // Rotate register pipeline; prefetch next iteration's B from L2.
        uint4 bcur[8];
#pragma unroll
        for (int q = 0; q < 8; ++q) bcur[q] = bnxt[q];
        if (it + 1 < NITER) loadB(bnxt, it + 1, nwarp, lane);

        if (kspair == 0) {
#pragma unroll
            for (int mf = 0; mf < 4; ++mf)
#pragma unroll
                for (int nf = 0; nf < 4; ++nf)
#pragma unroll
                    for (int c = 0; c < 4; ++c) acc[mf][nf][c] = 0.f;
        }

#pragma unroll
        for (int ksl = 0; ksl < 2; ++ksl) {
            const int ks = kspair * 2 + ksl;
            uint32_t ah[4][4], al[4][4];
#pragma unroll
            for (int mf = 0; mf < 4; ++mf) {
                int idx = (((mwarp * 4 + mf) * 16 + ks) * 32 + lane) * 4;
                *(uint4*)ah[mf] = *(const uint4*)(As + idx);
                *(uint4*)al[mf] = *(const uint4*)(As + 16384 + idx);
            }
#pragma unroll
            for (int mf = 0; mf < 4; ++mf)
#pragma unroll
                for (int nf = 0; nf < 4; ++nf) {
                    const uint32_t* bb = (const uint32_t*)&bcur[nf * 2 + ksl];
                    mma16816(acc[mf][nf], ah[mf], bb);        // hi*hi
                    mma16816(acc[mf][nf], ah[mf], bb + 2);    // hi*lo
                    mma16816(acc[mf][nf], al[mf], bb);        // lo*hi
                }
        }

        // End of n-tile: fold distances into running argmin (k ascending).
        if (kspair == 7) {
#pragma unroll
            for (int mf = 0; mf < 4; ++mf) {
#pragma unroll
                for (int nf = 0; nf < 4; ++nf) {
                    const int k0 = ntile * NT + (nwarp * 4 + nf) * 8 + tig * 2;
                    float c0 = __ldg(&g_csq[k0]);
                    float c1 = __ldg(&g_csq[k0 + 1]);
                    float m00 = fmaf(-2.f, acc[mf][nf][0], c0);
                    float m01 = fmaf(-2.f, acc[mf][nf][1], c1);
                    float m10 = fmaf(-2.f, acc[mf][nf][2], c0);
                    float m11 = fmaf(-2.f, acc[mf][nf][3], c1);
                    if (m00 < best[mf][0]) { best[mf][0] = m00; bidx[mf][0] = k0; }
                    if (m01 < best[mf][0]) { best[mf][0] = m01; bidx[mf][0] = k0 + 1; }
                    if (m10 < best[mf][1]) { best[mf][1] = m10; bidx[mf][1] = k0; }
                    if (m11 < best[mf][1]) { best[mf][1] = m11; bidx[mf][1] = k0 + 1; }
                }
            }
        }
    }

    // Reduce across the 4 tig lanes (same rows), lower index wins ties.
#pragma unroll
    for (int mf = 0; mf < 4; ++mf) {
#pragma unroll
        for (int hh = 0; hh < 2; ++hh) {
            float bv = best[mf][hh];
            int   bi = bidx[mf][hh];
#pragma unroll
            for (int off = 1; off <= 2; off <<= 1) {
                float ov = __shfl_xor_sync(0xffffffffu, bv, off);
                int   oi = __shfl_xor_sync(0xffffffffu, bi, off);
                if (ov < bv || (ov == bv && oi < bi)) { bv = ov; bi = oi; }
            }
            if (tig == 0) {
                int row = mwarp * 64 + mf * 16 + gid + hh * 8;
                unsigned long long key =
                    ((unsigned long long)fkey(bv) << 32) | (unsigned)bi;
                atomicMin(&red[row], key);
            }
        }
    }
    __syncthreads();
    if (tid < MT) g_ind[n0 + tid] = (int)(red[tid] & 0xFFFFFFFFu);
}

// ---------------------------------------------------------------------------
// Outputs: quantized_x_d, quantized_x, ind (exact fp32 op order for STE).
// ---------------------------------------------------------------------------
__global__ void vq_gather_kernel(const float* __restrict__ x,
                                 const float* __restrict__ E,
                                 float* __restrict__ out) {
    size_t tid = (size_t)blockIdx.x * blockDim.x + threadIdx.x;
    int n = (int)(tid & (NTOK - 1));
    int d = (int)(tid >> 14);
    int idx = g_ind[n];
    int b = n >> 10;
    int s = n & (S_ - 1);
    float q = E[(size_t)d * KC + idx];
    size_t xo = ((size_t)b * D_ + d) * S_ + s;
    float xv = x[xo];
    out[xo]       = xv + (q - xv);
    out[BDS + xo] = q;
    if (d == 0) out[2 * (size_t)BDS + n] = (float)idx;
}

// ---------------------------------------------------------------------------
extern "C" void kernel_launch(void* const* d_in, const int* in_sizes, int n_in,
                              void* d_out, int out_size) {
    const float* x = (const float*)d_in[0];   // [B, D, H, W] fp32
    const float* E = (const float*)d_in[1];   // [D, K] fp32
    float* out = (float*)d_out;

    cudaFuncSetAttribute(vq_mma_kernel,
                         cudaFuncAttributeMaxDynamicSharedMemorySize, SMEM_MAIN);

    vq_split_x<<<MB_TOT, 256>>>(x);
    vq_split_e<<<(NB_TOT * 16 * 32) / 256, 256>>>(E);
    vq_csq_kernel<<<KC / 256, 256>>>(E);
    vq_mma_kernel<<<NTOK / MT, 256, SMEM_MAIN>>>();
    vq_gather_kernel<<<(D_ * NTOK) / 256, 256>>>(x, E, out);
}

// round 8
// speedup vs baseline: 5.3973x; 1.0990x over previous
#include <cuda_runtime.h>
#include <cuda_fp16.h>
#include <cstdint>

// Problem constants
#define B_    16
#define D_    256
#define S_    1024
#define NTOK  16384
#define KC    8192
#define BDS   4194304

#define MB_TOT (NTOK / 16)        // 1024 token blocks of 16
#define KS_TOT (D_ / 16)          // 16 k-steps of 16
#define NB_TOT (KC / 8)           // 1024 code blocks of 8

// Main kernel tiling
#define MT     128                // tokens per block
#define NT     128                // codes per n-tile
#define NPARTS 8                  // codebook split per token tile
#define NT_PER_PART (KC / NT / NPARTS)   // 8 ntiles per part
#define NITERL (NT_PER_PART * 8)  // 64 local iterations (2 k-steps each)

// smem layout (bytes): A-tile (hi|lo) + reduction slots
#define SMEM_A_BYTES 131072       // [2 h][8 mb][16 ks][32 lane][4] u32
#define SMEM_RED     1024         // 128 x u64
#define SMEM_MAIN (SMEM_A_BYTES + SMEM_RED)

// Device scratch (allocations forbidden)
__device__ uint32_t g_Ah[MB_TOT * KS_TOT * 32 * 4];   // 8 MB
__device__ uint32_t g_Al[MB_TOT * KS_TOT * 32 * 4];   // 8 MB
__device__ uint32_t g_B [NB_TOT * KS_TOT * 32 * 4];   // 8 MB: {bh0,bh1,bl0,bl1}
__device__ float    g_csq[KC];
__device__ unsigned long long g_key[NTOK];            // packed (fkey(dist)<<32 | k)

// ---------------------------- helpers --------------------------------------
__device__ __forceinline__ uint32_t smem_u32(const void* p) {
    uint32_t a;
    asm("{ .reg .u64 t; cvta.to.shared.u64 t, %1; cvt.u32.u64 %0, t; }" : "=r"(a) : "l"(p));
    return a;
}
__device__ __forceinline__ void cpasync16(uint32_t dst, const void* src) {
    asm volatile("cp.async.cg.shared.global [%0], [%1], 16;" :: "r"(dst), "l"(src));
}
__device__ __forceinline__ void mma16816(float* c, const uint32_t* a, const uint32_t* b) {
    asm volatile("mma.sync.aligned.m16n8k16.row.col.f32.f16.f16.f32 "
                 "{%0,%1,%2,%3}, {%4,%5,%6,%7}, {%8,%9}, {%0,%1,%2,%3};"
                 : "+f"(c[0]), "+f"(c[1]), "+f"(c[2]), "+f"(c[3])
                 : "r"(a[0]), "r"(a[1]), "r"(a[2]), "r"(a[3]), "r"(b[0]), "r"(b[1]));
}
__device__ __forceinline__ uint32_t pack_h2(__half lo, __half hi) {
    __half2 h = __halves2half2(lo, hi);
    return *reinterpret_cast<uint32_t*>(&h);
}
__device__ __forceinline__ void split16(float v, __half& h, __half& l) {
    h = __float2half_rn(v);
    l = __float2half_rn(v - __half2float(h));
}
__device__ __forceinline__ unsigned int fkey(float f) {
    unsigned u = __float_as_uint(f);
    return (u & 0x80000000u) ? ~u : (u | 0x80000000u);
}

// ---------------------------------------------------------------------------
// Split x into fp16 hi/lo A-fragments (mma m16n8k16 row-major A layout).
// Also re-initializes g_key every launch (blocks 0..63).
// ---------------------------------------------------------------------------
__global__ void vq_split_x(const float* __restrict__ x) {
    __shared__ float xs[D_ * 16];            // [d][tok]
    const int mb = blockIdx.x;
    const int t0 = mb * 16;
    const int b  = t0 >> 10;
    const int s0 = t0 & (S_ - 1);
    const int tid = threadIdx.x;

    if (mb < NTOK / 256) g_key[mb * 256 + tid] = 0xFFFFFFFFFFFFFFFFULL;

    for (int i = tid; i < D_ * 16; i += 256) {
        int d = i >> 4, tok = i & 15;
        xs[d * 16 + tok] = x[((size_t)b * D_ + d) * S_ + s0 + tok];
    }
    __syncthreads();

    const size_t obase = (size_t)mb * (KS_TOT * 32 * 4);
    for (int oi = tid; oi < KS_TOT * 32 * 4; oi += 256) {
        int ks = oi >> 7, rem = oi & 127;
        int lane = rem >> 2, r = rem & 3;
        int gid = lane >> 2, tig = lane & 3;
        int row = gid + (r & 1) * 8;
        int c0  = ks * 16 + tig * 2 + (r >> 1) * 8;
        float v0 = xs[c0 * 16 + row];
        float v1 = xs[(c0 + 1) * 16 + row];
        __half h0, l0, h1, l1;
        split16(v0, h0, l0);
        split16(v1, h1, l1);
        g_Ah[obase + oi] = pack_h2(h0, h1);
        g_Al[obase + oi] = pack_h2(l0, l1);
    }
}

// ---------------------------------------------------------------------------
// Split E into interleaved fp16 hi/lo B-fragments (m16n8k16 col-major B).
// ---------------------------------------------------------------------------
__global__ void vq_split_e(const float* __restrict__ E) {
    int gidx = blockIdx.x * 256 + threadIdx.x;    // 0 .. NB_TOT*16*32
    int lane = gidx & 31;
    int ks   = (gidx >> 5) & 15;
    int nb   = gidx >> 9;
    int gid = lane >> 2, tig = lane & 3;
    int k = nb * 8 + gid;
    uint32_t frag[4];
#pragma unroll
    for (int r = 0; r < 2; ++r) {
        int d0 = ks * 16 + tig * 2 + r * 8;
        float v0 = E[(size_t)d0 * KC + k];
        float v1 = E[(size_t)(d0 + 1) * KC + k];
        __half h0, l0, h1, l1;
        split16(v0, h0, l0);
        split16(v1, h1, l1);
        frag[r]     = pack_h2(h0, h1);
        frag[2 + r] = pack_h2(l0, l1);
    }
    *(uint4*)&g_B[(size_t)gidx * 4] = *(uint4*)frag;
}

// ---------------------------------------------------------------------------
__global__ void vq_csq_kernel(const float* __restrict__ E) {
    int k = blockIdx.x * blockDim.x + threadIdx.x;
    float a = 0.f;
#pragma unroll 8
    for (int d = 0; d < D_; ++d) {
        float v = E[(size_t)d * KC + k];
        a = fmaf(v, v, a);
    }
    g_csq[k] = a;
}

// ---------------------------------------------------------------------------
// Main kernel: fp16-split mma.sync; block = (token-tile, codebook eighth).
// A resident in smem, B register-pipelined via LDG.128; barrier-free mainloop.
// Grid = 1024 fine-grained blocks -> fills all 148 SMs.
// ---------------------------------------------------------------------------
__device__ __forceinline__ void loadB(uint4* b, int it, int nwarp, int lane) {
    const int ntile = it >> 3, kspair = it & 7;
    const uint32_t* base = g_B +
        ((size_t)(((ntile * 16 + nwarp * 4) * 16 + kspair * 2) * 32 + lane)) * 4;
#pragma unroll
    for (int nf = 0; nf < 4; ++nf)
#pragma unroll
        for (int ksl = 0; ksl < 2; ++ksl)
            b[nf * 2 + ksl] = __ldg((const uint4*)(base + nf * 2048 + ksl * 128));
}

__global__ __launch_bounds__(256, 1) void vq_mma_kernel() {
    extern __shared__ char smem[];
    uint32_t* As = (uint32_t*)smem;
    unsigned long long* red = (unsigned long long*)(smem + SMEM_A_BYTES);
    const uint32_t sA = smem_u32(As);

    const int tid = threadIdx.x;
    const int wid = tid >> 5, lane = tid & 31;
    const int gid = lane >> 2, tig = lane & 3;
    const int mwarp = wid >> 2, nwarp = wid & 3;

    const int bx = blockIdx.x;                // 0..1023
    const int part   = bx & (NPARTS - 1);     // codebook eighth
    const int tileid = bx >> 3;               // token tile
    const int mb0 = tileid * 8;
    const int n0  = tileid * MT;
    const int it0 = part * NITERL;            // global iteration base

    for (int i = tid; i < MT; i += 256) red[i] = 0xFFFFFFFFFFFFFFFFULL;

    // Prologue: A resident tile (hi+lo, 128 KB) via cp.async; single barrier.
    {
        const uint32_t* srcH = g_Ah + (size_t)mb0 * (KS_TOT * 32 * 4);
        const uint32_t* srcL = g_Al + (size_t)mb0 * (KS_TOT * 32 * 4);
        for (int u = tid; u < 4096; u += 256) {
            cpasync16(sA + u * 16, srcH + u * 4);
            cpasync16(sA + 65536 + u * 16, srcL + u * 4);
        }
        asm volatile("cp.async.commit_group;" ::: "memory");
    }

    uint4 bnxt[8];
    loadB(bnxt, it0, nwarp, lane);            // overlaps the A cp.async

    asm volatile("cp.async.wait_group 0;" ::: "memory");
    __syncthreads();                           // last barrier before epilogue

    float best[4][2];
    int   bidx[4][2];
#pragma unroll
    for (int mf = 0; mf < 4; ++mf)
#pragma unroll
        for (int hh = 0; hh < 2; ++hh) { best[mf][hh] = 3.402823466e+38f; bidx[mf][hh] = 0; }

    float acc[4][4][4];

    for (int ii = 0; ii < NITERL; ++ii) {
        const int it = it0 + ii;
        const int ntile = it >> 3, kspair = it & 7;

        // Rotate register pipeline; prefetch next iteration's B from L2.
        uint4 bcur[8];
#pragma unroll
        for (int q = 0; q < 8; ++q) bcur[q] = bnxt[q];
        if (ii + 1 < NITERL) loadB(bnxt, it + 1, nwarp, lane);

        if (kspair == 0) {
#pragma unroll
            for (int mf = 0; mf < 4; ++mf)
#pragma unroll
                for (int nf = 0; nf < 4; ++nf)
#pragma unroll
                    for (int c = 0; c < 4; ++c) acc[mf][nf][c] = 0.f;
        }

#pragma unroll
        for (int ksl = 0; ksl < 2; ++ksl) {
            const int ks = kspair * 2 + ksl;
            uint32_t ah[4][4], al[4][4];
#pragma unroll
            for (int mf = 0; mf < 4; ++mf) {
                int idx = (((mwarp * 4 + mf) * 16 + ks) * 32 + lane) * 4;
                *(uint4*)ah[mf] = *(const uint4*)(As + idx);
                *(uint4*)al[mf] = *(const uint4*)(As + 16384 + idx);
            }
#pragma unroll
            for (int mf = 0; mf < 4; ++mf)
#pragma unroll
                for (int nf = 0; nf < 4; ++nf) {
                    const uint32_t* bb = (const uint32_t*)&bcur[nf * 2 + ksl];
                    mma16816(acc[mf][nf], ah[mf], bb);        // hi*hi
                    mma16816(acc[mf][nf], ah[mf], bb + 2);    // hi*lo
                    mma16816(acc[mf][nf], al[mf], bb);        // lo*hi
                }
        }

        // End of n-tile: fold distances into running argmin (k ascending).
        if (kspair == 7) {
#pragma unroll
            for (int mf = 0; mf < 4; ++mf) {
#pragma unroll
                for (int nf = 0; nf < 4; ++nf) {
                    const int k0 = ntile * NT + (nwarp * 4 + nf) * 8 + tig * 2;
                    float c0 = __ldg(&g_csq[k0]);
                    float c1 = __ldg(&g_csq[k0 + 1]);
                    float m00 = fmaf(-2.f, acc[mf][nf][0], c0);
                    float m01 = fmaf(-2.f, acc[mf][nf][1], c1);
                    float m10 = fmaf(-2.f, acc[mf][nf][2], c0);
                    float m11 = fmaf(-2.f, acc[mf][nf][3], c1);
                    if (m00 < best[mf][0]) { best[mf][0] = m00; bidx[mf][0] = k0; }
                    if (m01 < best[mf][0]) { best[mf][0] = m01; bidx[mf][0] = k0 + 1; }
                    if (m10 < best[mf][1]) { best[mf][1] = m10; bidx[mf][1] = k0; }
                    if (m11 < best[mf][1]) { best[mf][1] = m11; bidx[mf][1] = k0 + 1; }
                }
            }
        }
    }

    // Two-level argmin merge: shfl across tig lanes -> smem -> global key.
#pragma unroll
    for (int mf = 0; mf < 4; ++mf) {
#pragma unroll
        for (int hh = 0; hh < 2; ++hh) {
            float bv = best[mf][hh];
            int   bi = bidx[mf][hh];
#pragma unroll
            for (int off = 1; off <= 2; off <<= 1) {
                float ov = __shfl_xor_sync(0xffffffffu, bv, off);
                int   oi = __shfl_xor_sync(0xffffffffu, bi, off);
                if (ov < bv || (ov == bv && oi < bi)) { bv = ov; bi = oi; }
            }
            if (tig == 0) {
                int row = mwarp * 64 + mf * 16 + gid + hh * 8;
                unsigned long long key =
                    ((unsigned long long)fkey(bv) << 32) | (unsigned)bi;
                atomicMin(&red[row], key);
            }
        }
    }
    __syncthreads();
    if (tid < MT) atomicMin(&g_key[n0 + tid], red[tid]);
}

// ---------------------------------------------------------------------------
// Outputs: quantized_x_d, quantized_x, ind (exact fp32 op order for STE).
// ---------------------------------------------------------------------------
__global__ void vq_gather_kernel(const float* __restrict__ x,
                                 const float* __restrict__ E,
                                 float* __restrict__ out) {
    size_t tid = (size_t)blockIdx.x * blockDim.x + threadIdx.x;
    int n = (int)(tid & (NTOK - 1));
    int d = (int)(tid >> 14);
    int idx = (int)(g_key[n] & 0xFFFFFFFFu);
    int b = n >> 10;
    int s = n & (S_ - 1);
    float q = E[(size_t)d * KC + idx];
    size_t xo = ((size_t)b * D_ + d) * S_ + s;
    float xv = x[xo];
    out[xo]       = xv + (q - xv);
    out[BDS + xo] = q;
    if (d == 0) out[2 * (size_t)BDS + n] = (float)idx;
}

// ---------------------------------------------------------------------------
extern "C" void kernel_launch(void* const* d_in, const int* in_sizes, int n_in,
                              void* d_out, int out_size) {
    const float* x = (const float*)d_in[0];   // [B, D, H, W] fp32
    const float* E = (const float*)d_in[1];   // [D, K] fp32
    float* out = (float*)d_out;

    cudaFuncSetAttribute(vq_mma_kernel,
                         cudaFuncAttributeMaxDynamicSharedMemorySize, SMEM_MAIN);

    vq_split_x<<<MB_TOT, 256>>>(x);
    vq_split_e<<<(NB_TOT * 16 * 32) / 256, 256>>>(E);
    vq_csq_kernel<<<KC / 256, 256>>>(E);
    vq_mma_kernel<<<(NTOK / MT) * NPARTS, 256, SMEM_MAIN>>>();
    vq_gather_kernel<<<(D_ * NTOK) / 256, 256>>>(x, E, out);
}